// round 6
// baseline (speedup 1.0000x reference)
#include <cuda_runtime.h>

// lp[r,p] = sum_f w[p,f]^2 * sum_e x[r,f,e]^2
// x: [R=32768, F=64, E=16] fp32 (row = 1024 contiguous floats = 4KB)
// w: [P=10, F=64] fp32 ; out: [R, 10] fp32
//
// Warp-per-row, TWO half-phases of 4 float4 loads each (16 regs for v[]
// instead of 32) so the kernel fits a 40-register cap -> 6 blocks/SM
// (48 warps). lane = 4q + c. Phase h, step j in 0..3: float4 index
// (4h+j)*32 + lane lies in f = 8*(4h+j) + q, e-quarter c. Quad butterfly
// (xor 1,2) completes the e-sum; 3 accumulators per lane own p in
// {c, c+4, c+8} (p>=10 padded to zero). Final xor 4,8,16 butterfly sums
// over q-groups; lanes 0..9 store out[r*10 + lane].

#define R_ROWS 32768
#define F_DIM 64
#define E_DIM 16
#define P_DIM 10
#define P_PAD 12
#define THREADS 256
#define BLOCKS 888   // 6 blocks/SM * 148 SMs, single wave; grid-stride rows

__global__ __launch_bounds__(THREADS, 6) void ip_fused_kernel(
    const float* __restrict__ x,
    const float* __restrict__ w,
    float* __restrict__ out)
{
    // [f][12] layout: word addr = f*12 + p. Access (8j+q)*12 + 4t + c:
    // banks (12q+c) mod 32 all distinct across the warp -> conflict-free.
    __shared__ float sh_wsq[F_DIM * P_PAD];

    for (int i = threadIdx.x; i < F_DIM * P_PAD; i += THREADS) {
        const int f = i / P_PAD;
        const int p = i - f * P_PAD;
        float v = (p < P_DIM) ? w[p * F_DIM + f] : 0.0f;
        sh_wsq[i] = v * v;
    }
    __syncthreads();

    const int lane = threadIdx.x & 31;
    const int q = lane >> 2;
    const int c = lane & 3;
    const int warp = threadIdx.x >> 5;
    const int gwarp = blockIdx.x * (THREADS / 32) + warp;
    const int nwarp = BLOCKS * (THREADS / 32);

    for (int r = gwarp; r < R_ROWS; r += nwarp) {
        const float4* __restrict__ xr =
            reinterpret_cast<const float4*>(x + (size_t)r * (F_DIM * E_DIM));

        float acc0 = 0.0f, acc1 = 0.0f, acc2 = 0.0f;

#pragma unroll
        for (int h = 0; h < 2; ++h) {
            // 4-deep batch of streaming loads for this half-row.
            float4 v[4];
#pragma unroll
            for (int j = 0; j < 4; ++j) {
                v[j] = __ldcs(&xr[(4 * h + j) * 32 + lane]);
            }

#pragma unroll
            for (int j = 0; j < 4; ++j) {
                float4 a = v[j];
                float s = fmaf(a.x, a.x,
                          fmaf(a.y, a.y,
                          fmaf(a.z, a.z, a.w * a.w)));
                // complete the sum over e (16 values span the quad)
                s += __shfl_xor_sync(0xFFFFFFFFu, s, 1);
                s += __shfl_xor_sync(0xFFFFFFFFu, s, 2);
                const float* wrow = &sh_wsq[(8 * (4 * h + j) + q) * P_PAD + c];
                acc0 = fmaf(wrow[0], s, acc0);
                acc1 = fmaf(wrow[4], s, acc1);
                acc2 = fmaf(wrow[8], s, acc2);
            }
        }

        // reduce across the 8 quads (sum over f-groups), c preserved
#pragma unroll
        for (int m = 4; m <= 16; m <<= 1) {
            acc0 += __shfl_xor_sync(0xFFFFFFFFu, acc0, m);
            acc1 += __shfl_xor_sync(0xFFFFFFFFu, acc1, m);
            acc2 += __shfl_xor_sync(0xFFFFFFFFu, acc2, m);
        }

        if (lane < P_DIM) {
            float res = (lane < 4) ? acc0 : (lane < 8) ? acc1 : acc2;
            out[(size_t)r * P_DIM + lane] = res;
        }
    }
}

extern "C" void kernel_launch(void* const* d_in, const int* in_sizes, int n_in,
                              void* d_out, int out_size)
{
    const float* x = (const float*)d_in[0];   // [32768, 64, 16]
    const float* w = (const float*)d_in[1];   // [10, 64]
    float* out = (float*)d_out;               // [32768, 10]
    (void)in_sizes; (void)n_in; (void)out_size;

    ip_fused_kernel<<<BLOCKS, THREADS>>>(x, w, out);
}